// round 16
// baseline (speedup 1.0000x reference)
#include <cuda_runtime.h>

// SubglacialDrainageSystem: 64x64 grid, 5-point elliptic solve + closed-form
// sheet update. Single block, 512 thr, WARP-BAND layout (warp w: rows
// 4w..4w+3, lane l: cols 2l,2l+1). fp32 Chronopoulos-Gear PCG + degree-8
// Chebyshev preconditioner; fp64 refinement. R15: all inner fp32 math in
// PACKED f32x2 (Blackwell FFMA2) -> halves fma-pipe instruction count.

#define NN      4096
#define NPAD    (NN + 128)
#define NT      512
#define PER     8
#define CHEB_D  8

#define K_COND    0.01
#define SEC_PER_A 31556926.0
#define HR_       0.1
#define LR_       2.0
#define A_        5e-25

typedef unsigned long long ull;

#define FMA2(d, a, b, c) \
    asm("fma.rn.f32x2 %0, %1, %2, %3;" : "=l"(d) : "l"(a), "l"(b), "l"(c))
#define MUL2(d, a, b) \
    asm("mul.rn.f32x2 %0, %1, %2;" : "=l"(d) : "l"(a), "l"(b))
#define ADD2(d, a, b) \
    asm("add.rn.f32x2 %0, %1, %2;" : "=l"(d) : "l"(a), "l"(b))
#define PACK2(d, lo, hi) \
    asm("mov.b64 %0, {%1, %2};" : "=l"(d) : "f"(lo), "f"(hi))
#define UNPACK2(lo, hi, v) \
    asm("mov.b64 {%0, %1}, %2;" : "=f"(lo), "=f"(hi) : "l"(v))

struct Smem {
    double cEd[NPAD];
    double cSd[NPAD];
    double Zs[NPAD];
    double Bt[NN];
    double isd[NN];
    double red[40];
    float4 red4[16];
    float  gTop[2][18][64];   // [buf][warp+1][col] row 4w pair; rows 0,17 zero
    float  gBot[2][18][64];   // [buf][warp+1][col] row 4w+3 pair
};

__device__ __forceinline__ double bred_d(double v, double* red, int tid) {
    #pragma unroll
    for (int o = 16; o > 0; o >>= 1) v += __shfl_down_sync(0xffffffffu, v, o);
    if ((tid & 31) == 0) red[tid >> 5] = v;
    __syncthreads();
    if (tid < 32) {
        double s = red[tid];
        #pragma unroll
        for (int o = 16; o > 0; o >>= 1) s += __shfl_down_sync(0xffffffffu, s, o);
        if (tid == 0) red[36] = s;
    }
    __syncthreads();
    return red[36];
}

__device__ __forceinline__ double bred_dmax(double v, double* red, int tid) {
    #pragma unroll
    for (int o = 16; o > 0; o >>= 1) v = fmax(v, __shfl_down_sync(0xffffffffu, v, o));
    if ((tid & 31) == 0) red[tid >> 5] = v;
    __syncthreads();
    if (tid < 32) {
        double s = red[tid];
        #pragma unroll
        for (int o = 16; o > 0; o >>= 1) s = fmax(s, __shfl_down_sync(0xffffffffu, s, o));
        if (tid == 0) red[36] = s;
    }
    __syncthreads();
    return red[36];
}

__device__ __forceinline__ float3 bred3f(float a, float b, float c,
                                         float4* red4, int tid) {
    #pragma unroll
    for (int o = 16; o > 0; o >>= 1) {
        a += __shfl_down_sync(0xffffffffu, a, o);
        b += __shfl_down_sync(0xffffffffu, b, o);
        c += __shfl_down_sync(0xffffffffu, c, o);
    }
    if ((tid & 31) == 0) red4[tid >> 5] = make_float4(a, b, c, 0.f);
    __syncthreads();
    float4 v = red4[tid & 15];
    float x = v.x, y = v.y, z = v.z;
    #pragma unroll
    for (int o = 8; o > 0; o >>= 1) {
        x += __shfl_xor_sync(0xffffffffu, x, o);
        y += __shfl_xor_sync(0xffffffffu, y, o);
        z += __shfl_xor_sync(0xffffffffu, z, o);
    }
    return make_float3(x, y, z);
}

__global__ void __launch_bounds__(NT, 1)
sgd_kernel(const float* __restrict__ base, const float* __restrict__ over,
           const float* __restrict__ melt, const float* __restrict__ sheet,
           const float* __restrict__ pot,  const float* __restrict__ svel,
           const float* __restrict__ llen, const int* __restrict__ lan,
           const int* __restrict__ inflow, float* __restrict__ out)
{
    extern __shared__ unsigned char smraw[];
    Smem& S = *reinterpret_cast<Smem*>(smraw);
    const int tid = threadIdx.x;
    const int wrp = tid >> 5;
    const int ln  = tid & 31;

    // ---- 1. zero arrays ----
    for (int k = tid; k < NPAD; k += NT) { S.cEd[k] = 0.0; S.cSd[k] = 0.0; S.Zs[k] = 0.0; }
    {
        float* g = &S.gTop[0][0][0];
        for (int k = tid; k < 2 * 2 * 18 * 64; k += NT) g[k] = 0.f;
    }
    if (tid < 40) S.red[tid] = 0.0;
    __syncthreads();

    // ---- 2. raw link coefficients (fp64) ----
    #pragma unroll
    for (int nn = 0; nn < PER; nn++) {
        int i = tid + nn * NT;
        int col = i & 63, row = i >> 6;
        double pi = (double)pot[i], hi = (double)sheet[i];
        if (col < 63) {
            double len = (double)llen[row * 63 + col];
            double s = 0.5 * (hi + (double)sheet[i + 1]);
            double g = fabs(pi - (double)pot[i + 1]) / len;
            S.cEd[i + 64] = -K_COND * (s * sqrt(sqrt(s))) * len / sqrt(g);
        }
        if (row < 63) {
            double len = (double)llen[4032 + row * 64 + col];
            double s = 0.5 * (hi + (double)sheet[i + 64]);
            double g = fabs(pi - (double)pot[i + 64]) / len;
            S.cSd[i + 64] = -K_COND * (s * sqrt(sqrt(s))) * len / sqrt(g);
        }
    }
    __syncthreads();

    // ---- 3. diag, rhs, scaling factors, warm start ----
    #pragma unroll
    for (int nn = 0; nn < PER; nn++) {
        int i = tid + nn * NT;
        int col = i & 63, row = i >> 6;
        bool dir = (inflow[i] == 1);
        double cEi = S.cEd[i + 64];
        double cWi = S.cEd[i + 63];
        double cSi = S.cSd[i + 64];
        double cNi = S.cSd[i];
        double d, b;
        double dval = (double)base[i] - (double)over[i];
        if (dir) {
            d = 1.0; b = dval;
        } else {
            d = -(cEi + cWi + cSi + cNi);
            b = (double)melt[i];
            if (col < 63 && inflow[i + 1] == 1)
                b -= cEi * ((double)base[i + 1] - (double)over[i + 1]);
            if (col > 0 && inflow[i - 1] == 1)
                b -= cWi * ((double)base[i - 1] - (double)over[i - 1]);
            if (row < 63 && inflow[i + 64] == 1)
                b -= cSi * ((double)base[i + 64] - (double)over[i + 64]);
            if (row > 0 && inflow[i - 64] == 1)
                b -= cNi * ((double)base[i - 64] - (double)over[i - 64]);
        }
        double sq = sqrt(d);
        double is = 1.0 / sq;
        S.isd[i] = is;
        S.Bt[i] = b * is;
        S.Zs[i + 64] = dval * sq;
    }
    __syncthreads();

    // ---- 4. symmetric scaling + decoupling + Gershgorin ----
    #pragma unroll
    for (int nn = 0; nn < PER; nn++) {
        int i = tid + nn * NT;
        int col = i & 63, row = i >> 6;
        bool dirI = (inflow[i] == 1);
        if (col < 63) {
            bool dirE = (inflow[i + 1] == 1);
            S.cEd[i + 64] = (dirI || dirE) ? 0.0
                          : S.cEd[i + 64] * S.isd[i] * S.isd[i + 1];
        }
        if (row < 63) {
            bool dirS = (inflow[i + 64] == 1);
            S.cSd[i + 64] = (dirI || dirS) ? 0.0
                          : S.cSd[i + 64] * S.isd[i] * S.isd[i + 64];
        }
    }
    __syncthreads();
    double gmax = 1.0;
    #pragma unroll
    for (int nn = 0; nn < PER; nn++) {
        int i = tid + nn * NT;
        double srow = 1.0 - (S.cEd[i + 64] + S.cEd[i + 63]
                           + S.cSd[i + 64] + S.cSd[i]);
        gmax = fmax(gmax, srow);
    }
    const double lmax = bred_dmax(gmax, S.red, tid) * 1.0005;

    // Chebyshev constants (validated interval [b/25, b])
    const float bF = (float)lmax;
    const float aF = bF * 0.04f;
    const float thetaF = 0.5f * (bF + aF);
    const float deltaF = 0.5f * (bF - aF);
    const float inv_th = 1.0f / thetaF;
    const float sigma1 = thetaF / deltaF;
    const float rho0C  = 1.0f / sigma1;
    const float two_sg = 2.0f * sigma1;
    const float two_id = 2.0f / deltaF;

    // ---- 5. packed band coefficients ----
    const int row0 = wrp * 4, col0 = ln * 2;
    int jbase[4];
    ull cA[4], cB[4], cSp[4], cN0p;   // cA=(cW,cE0) cB=(cE0,cE1) cSp=(cS0,cS1)
    #pragma unroll
    for (int rr = 0; rr < 4; rr++) {
        int j = (row0 + rr) * 64 + col0 + 64;
        jbase[rr] = j;
        float e0 = (float)S.cEd[j], e1 = (float)S.cEd[j + 1];
        float w0 = (float)S.cEd[j - 1];
        float s0 = (float)S.cSd[j], s1 = (float)S.cSd[j + 1];
        PACK2(cA[rr], w0, e0);
        PACK2(cB[rr], e0, e1);
        PACK2(cSp[rr], s0, s1);
    }
    {
        float n0 = (float)S.cSd[jbase[0] - 64], n1 = (float)S.cSd[jbase[0] - 63];
        PACK2(cN0p, n0, n1);
    }
    ull NEG1, INVTH;
    PACK2(NEG1, -1.f, -1.f);
    PACK2(INVTH, inv_th, inv_th);

    double sb = 0.0;
    #pragma unroll
    for (int rr = 0; rr < 4; rr++) {
        double v0 = S.Bt[jbase[rr] - 64], v1 = S.Bt[jbase[rr] - 63];
        sb += v0 * v0 + v1 * v1;
    }
    const double rzb = bred_d(sb, S.red, tid);
    const double rz_target = rzb * 1e-16;

    // packed SpMV: t2 = A~ v2 ; ghosts (8B) from buffer buf
    auto spmv2 = [&](const ull v2[4], ull t2[4], int buf) {
        ull gN = *(const ull*)&S.gBot[buf][wrp][col0];      // row row0-1 pair
        ull gS = *(const ull*)&S.gTop[buf][wrp + 2][col0];  // row row0+4 pair
        #pragma unroll
        for (int rr = 0; rr < 4; rr++) {
            float vl, vr;
            UNPACK2(vl, vr, v2[rr]);
            float vW = __shfl_up_sync(0xffffffffu, vr, 1);
            float vE = __shfl_down_sync(0xffffffffu, vl, 1);
            ull xA, xB;
            PACK2(xA, vW, vl);
            PACK2(xB, vr, vE);
            ull n2 = (rr == 0) ? gN : v2[rr - 1];
            ull s2 = (rr == 3) ? gS : v2[rr + 1];
            ull cn = (rr == 0) ? cN0p : cSp[rr - 1];
            ull t;
            FMA2(t, cA[rr], xA, v2[rr]);
            FMA2(t, cB[rr], xB, t);
            FMA2(t, cn, n2, t);
            FMA2(t, cSp[rr], s2, t);
            t2[rr] = t;
        }
    };
    auto stage2 = [&](const ull v2[4], int buf) {
        *(ull*)&S.gTop[buf][wrp + 1][col0] = v2[0];
        *(ull*)&S.gBot[buf][wrp + 1][col0] = v2[3];
    };

    // ---- 6. outer refinement passes ----
    for (int pass = 0; pass < 6; ++pass) {
        // fp64 residual (band mapping)
        double rdv[8];
        double rr64 = 0.0;
        #pragma unroll
        for (int rr = 0; rr < 4; rr++) {
            #pragma unroll
            for (int cc = 0; cc < 2; cc++) {
                int j = jbase[rr] + cc;
                double qd = S.Zs[j]
                          + S.cEd[j]      * S.Zs[j + 1]
                          + S.cEd[j - 1]  * S.Zs[j - 1]
                          + S.cSd[j]      * S.Zs[j + 64]
                          + S.cSd[j - 64] * S.Zs[j - 64];
                double rv = S.Bt[j - 64] - qd;
                rdv[rr*2+cc] = rv;
                rr64 += rv * rv;
            }
        }
        rr64 = bred_d(rr64, S.red, tid);
        if (!(rr64 > rz_target)) break;

        ull r2[4], p2[4], q2[4], dx2[4];
        #pragma unroll
        for (int rr = 0; rr < 4; rr++) {
            PACK2(r2[rr], (float)rdv[rr*2+0], (float)rdv[rr*2+1]);
            p2[rr] = 0ull; q2[rr] = 0ull; dx2[rr] = 0ull;
        }
        const float tolp = fmaxf((float)rz_target, (float)rr64 * 1e-11f);
        const int cap = (pass == 0) ? 160 : 80;
        float rho_old = 1.f, alpha_old = 1.f;
        float rrchk = (float)rr64;

        for (int it = 0; it < cap; ++it) {
            // --- z = P_D(A) r, w = A z (Chebyshev, dot-free, packed) ---
            ull d2[4], z2[4], rin2[4], w2[4];
            #pragma unroll
            for (int rr = 0; rr < 4; rr++) {
                MUL2(d2[rr], r2[rr], INVTH);
                z2[rr] = d2[rr];
                rin2[rr] = r2[rr];
                w2[rr] = 0ull;
            }
            stage2(d2, 0);
            __syncthreads();
            float rhoC = rho0C;
            int buf = 0;
            #pragma unroll 1
            for (int k = 1; k <= CHEB_D; k++) {
                ull t2[4];
                spmv2(d2, t2, buf);
                float rhoN = __fdividef(1.f, two_sg - rhoC);
                float c1 = rhoN * rhoC, c2 = two_id * rhoN;
                ull c1p, c2p;
                PACK2(c1p, c1, c1);
                PACK2(c2p, c2, c2);
                #pragma unroll
                for (int rr = 0; rr < 4; rr++) {
                    FMA2(rin2[rr], t2[rr], NEG1, rin2[rr]);   // rin -= t
                    ADD2(w2[rr], w2[rr], t2[rr]);             // wacc += t
                    ull tmp;
                    MUL2(tmp, rin2[rr], c2p);
                    FMA2(d2[rr], d2[rr], c1p, tmp);           // d = c1*d + c2*rin
                    ADD2(z2[rr], z2[rr], d2[rr]);             // z += d
                }
                rhoC = rhoN;
                buf ^= 1;
                stage2(d2, buf);
                __syncthreads();
            }
            {
                ull t2[4];
                spmv2(d2, t2, buf);
                #pragma unroll
                for (int rr = 0; rr < 4; rr++) ADD2(w2[rr], w2[rr], t2[rr]);
            }

            // --- fused dots: rho=(r,z), mu=(z,w), rr=(r,r), packed partials ---
            ull apr = 0ull, apm = 0ull, aprr = 0ull;
            #pragma unroll
            for (int rr = 0; rr < 4; rr++) {
                FMA2(apr,  r2[rr], z2[rr], apr);
                FMA2(apm,  z2[rr], w2[rr], apm);
                FMA2(aprr, r2[rr], r2[rr], aprr);
            }
            float prL, prH, pmL, pmH, prrL, prrH;
            UNPACK2(prL, prH, apr);
            UNPACK2(pmL, pmH, apm);
            UNPACK2(prrL, prrH, aprr);
            float3 ds = bred3f(prL + prH, pmL + pmH, prrL + prrH, S.red4, tid);
            float rho = ds.x, mu = ds.y, rrf = ds.z;

            if (!(rrf > tolp)) break;
            if ((it & 15) == 15) {
                if (rrf > 0.9f * rrchk) break;
                rrchk = rrf;
            }
            if (!(rho > 0.f) || !(mu > 0.f)) break;

            float beta  = (it == 0) ? 0.f : __fdividef(rho, rho_old);
            float denom = mu - beta * __fdividef(rho, alpha_old);
            if (!(denom > 0.f)) break;
            float alpha = __fdividef(rho, denom);
            rho_old = rho; alpha_old = alpha;

            ull betap, alphap, nalphap;
            PACK2(betap, beta, beta);
            PACK2(alphap, alpha, alpha);
            PACK2(nalphap, -alpha, -alpha);
            #pragma unroll
            for (int rr = 0; rr < 4; rr++) {
                FMA2(p2[rr], p2[rr], betap, z2[rr]);      // p = z + beta p
                FMA2(q2[rr], q2[rr], betap, w2[rr]);      // q = w + beta q
                FMA2(dx2[rr], p2[rr], alphap, dx2[rr]);   // dx += alpha p
                FMA2(r2[rr], q2[rr], nalphap, r2[rr]);    // r -= alpha q
            }
            // next iter's stage(buf0) is WAR-safe: bred3f sync separates
        }

        __syncthreads();
        #pragma unroll
        for (int rr = 0; rr < 4; rr++) {
            float d0, d1;
            UNPACK2(d0, d1, dx2[rr]);
            S.Zs[jbase[rr] + 0] += (double)d0;
            S.Zs[jbase[rr] + 1] += (double)d1;
        }
        __syncthreads();
    }

    // ---- 7. outputs ----
    const double dtf = 3600.0;
    #pragma unroll
    for (int rr = 0; rr < 4; rr++) {
        #pragma unroll
        for (int cc = 0; cc < 2; cc++) {
            int i = jbase[rr] - 64 + cc;
            double x = S.Zs[i + 64] * S.isd[i];
            out[i] = (float)x;
            double P = (double)base[i] - x;
            const int* la = lan + 4 * i;
            double ssum = 0.0; int cnt = 0;
            #pragma unroll
            for (int k = 0; k < 4; k++) {
                int l = la[k];
                if (l >= 0) { ssum += (double)svel[l]; cnt++; }
            }
            double sliding = fabs(ssum / SEC_PER_A) / (double)(cnt > 0 ? cnt : 1);
            double nh = ((double)sheet[i] + dtf * sliding * HR_ / LR_)
                      / (1.0 + dtf * (sliding / LR_ + A_ * P * P * P));
            out[NN + i] = (float)nh;
        }
    }
}

extern "C" void kernel_launch(void* const* d_in, const int* in_sizes, int n_in,
                              void* d_out, int out_size)
{
    const float* base  = (const float*)d_in[0];
    const float* over  = (const float*)d_in[1];
    const float* melt  = (const float*)d_in[2];
    const float* sheet = (const float*)d_in[3];
    const float* pot   = (const float*)d_in[4];
    const float* svel  = (const float*)d_in[5];
    const float* llen  = (const float*)d_in[6];
    const int*   lan   = (const int*)d_in[9];
    const int*   infl  = (const int*)d_in[10];
    float* out = (float*)d_out;

    int smem = (int)sizeof(Smem);
    cudaFuncSetAttribute(sgd_kernel, cudaFuncAttributeMaxDynamicSharedMemorySize, smem);
    sgd_kernel<<<1, NT, smem>>>(base, over, melt, sheet, pot, svel, llen, lan, infl, out);
}

// round 17
// speedup vs baseline: 1.0316x; 1.0316x over previous
#include <cuda_runtime.h>

// SubglacialDrainageSystem: 64x64 grid, 5-point elliptic solve + closed-form
// sheet update. Single block, 512 thr, WARP-BAND layout (warp w: rows
// 4w..4w+3, lane l: cols 2l,2l+1). fp32 Chronopoulos-Gear PCG + degree-10
// Chebyshev preconditioner on WIDE interval [b/120, b] (covers all but ~11
// low modes -> few CG outer iters); packed f32x2 math; fp64 refinement.

#define NN      4096
#define NPAD    (NN + 128)
#define NT      512
#define PER     8
#define CHEB_D  10

#define K_COND    0.01
#define SEC_PER_A 31556926.0
#define HR_       0.1
#define LR_       2.0
#define A_        5e-25

typedef unsigned long long ull;

#define FMA2(d, a, b, c) \
    asm("fma.rn.f32x2 %0, %1, %2, %3;" : "=l"(d) : "l"(a), "l"(b), "l"(c))
#define MUL2(d, a, b) \
    asm("mul.rn.f32x2 %0, %1, %2;" : "=l"(d) : "l"(a), "l"(b))
#define ADD2(d, a, b) \
    asm("add.rn.f32x2 %0, %1, %2;" : "=l"(d) : "l"(a), "l"(b))
#define PACK2(d, lo, hi) \
    asm("mov.b64 %0, {%1, %2};" : "=l"(d) : "f"(lo), "f"(hi))
#define UNPACK2(lo, hi, v) \
    asm("mov.b64 {%0, %1}, %2;" : "=f"(lo), "=f"(hi) : "l"(v))

struct Smem {
    double cEd[NPAD];
    double cSd[NPAD];
    double Zs[NPAD];
    double Bt[NN];
    double isd[NN];
    double red[40];
    float4 red4[16];
    float  gTop[2][18][64];   // [buf][warp+1][col] row 4w pair; rows 0,17 zero
    float  gBot[2][18][64];   // [buf][warp+1][col] row 4w+3 pair
};

__device__ __forceinline__ double bred_d(double v, double* red, int tid) {
    #pragma unroll
    for (int o = 16; o > 0; o >>= 1) v += __shfl_down_sync(0xffffffffu, v, o);
    if ((tid & 31) == 0) red[tid >> 5] = v;
    __syncthreads();
    if (tid < 32) {
        double s = red[tid];
        #pragma unroll
        for (int o = 16; o > 0; o >>= 1) s += __shfl_down_sync(0xffffffffu, s, o);
        if (tid == 0) red[36] = s;
    }
    __syncthreads();
    return red[36];
}

__device__ __forceinline__ double bred_dmax(double v, double* red, int tid) {
    #pragma unroll
    for (int o = 16; o > 0; o >>= 1) v = fmax(v, __shfl_down_sync(0xffffffffu, v, o));
    if ((tid & 31) == 0) red[tid >> 5] = v;
    __syncthreads();
    if (tid < 32) {
        double s = red[tid];
        #pragma unroll
        for (int o = 16; o > 0; o >>= 1) s = fmax(s, __shfl_down_sync(0xffffffffu, s, o));
        if (tid == 0) red[36] = s;
    }
    __syncthreads();
    return red[36];
}

__device__ __forceinline__ float3 bred3f(float a, float b, float c,
                                         float4* red4, int tid) {
    #pragma unroll
    for (int o = 16; o > 0; o >>= 1) {
        a += __shfl_down_sync(0xffffffffu, a, o);
        b += __shfl_down_sync(0xffffffffu, b, o);
        c += __shfl_down_sync(0xffffffffu, c, o);
    }
    if ((tid & 31) == 0) red4[tid >> 5] = make_float4(a, b, c, 0.f);
    __syncthreads();
    float4 v = red4[tid & 15];
    float x = v.x, y = v.y, z = v.z;
    #pragma unroll
    for (int o = 8; o > 0; o >>= 1) {
        x += __shfl_xor_sync(0xffffffffu, x, o);
        y += __shfl_xor_sync(0xffffffffu, y, o);
        z += __shfl_xor_sync(0xffffffffu, z, o);
    }
    return make_float3(x, y, z);
}

__global__ void __launch_bounds__(NT, 1)
sgd_kernel(const float* __restrict__ base, const float* __restrict__ over,
           const float* __restrict__ melt, const float* __restrict__ sheet,
           const float* __restrict__ pot,  const float* __restrict__ svel,
           const float* __restrict__ llen, const int* __restrict__ lan,
           const int* __restrict__ inflow, float* __restrict__ out)
{
    extern __shared__ unsigned char smraw[];
    Smem& S = *reinterpret_cast<Smem*>(smraw);
    const int tid = threadIdx.x;
    const int wrp = tid >> 5;
    const int ln  = tid & 31;

    // ---- 1. zero arrays ----
    for (int k = tid; k < NPAD; k += NT) { S.cEd[k] = 0.0; S.cSd[k] = 0.0; S.Zs[k] = 0.0; }
    {
        float* g = &S.gTop[0][0][0];
        for (int k = tid; k < 2 * 2 * 18 * 64; k += NT) g[k] = 0.f;
    }
    if (tid < 40) S.red[tid] = 0.0;
    __syncthreads();

    // ---- 2. raw link coefficients (fp64) ----
    #pragma unroll
    for (int nn = 0; nn < PER; nn++) {
        int i = tid + nn * NT;
        int col = i & 63, row = i >> 6;
        double pi = (double)pot[i], hi = (double)sheet[i];
        if (col < 63) {
            double len = (double)llen[row * 63 + col];
            double s = 0.5 * (hi + (double)sheet[i + 1]);
            double g = fabs(pi - (double)pot[i + 1]) / len;
            S.cEd[i + 64] = -K_COND * (s * sqrt(sqrt(s))) * len / sqrt(g);
        }
        if (row < 63) {
            double len = (double)llen[4032 + row * 64 + col];
            double s = 0.5 * (hi + (double)sheet[i + 64]);
            double g = fabs(pi - (double)pot[i + 64]) / len;
            S.cSd[i + 64] = -K_COND * (s * sqrt(sqrt(s))) * len / sqrt(g);
        }
    }
    __syncthreads();

    // ---- 3. diag, rhs, scaling factors, warm start ----
    #pragma unroll
    for (int nn = 0; nn < PER; nn++) {
        int i = tid + nn * NT;
        int col = i & 63, row = i >> 6;
        bool dir = (inflow[i] == 1);
        double cEi = S.cEd[i + 64];
        double cWi = S.cEd[i + 63];
        double cSi = S.cSd[i + 64];
        double cNi = S.cSd[i];
        double d, b;
        double dval = (double)base[i] - (double)over[i];
        if (dir) {
            d = 1.0; b = dval;
        } else {
            d = -(cEi + cWi + cSi + cNi);
            b = (double)melt[i];
            if (col < 63 && inflow[i + 1] == 1)
                b -= cEi * ((double)base[i + 1] - (double)over[i + 1]);
            if (col > 0 && inflow[i - 1] == 1)
                b -= cWi * ((double)base[i - 1] - (double)over[i - 1]);
            if (row < 63 && inflow[i + 64] == 1)
                b -= cSi * ((double)base[i + 64] - (double)over[i + 64]);
            if (row > 0 && inflow[i - 64] == 1)
                b -= cNi * ((double)base[i - 64] - (double)over[i - 64]);
        }
        double sq = sqrt(d);
        double is = 1.0 / sq;
        S.isd[i] = is;
        S.Bt[i] = b * is;
        S.Zs[i + 64] = dval * sq;
    }
    __syncthreads();

    // ---- 4. symmetric scaling + decoupling + Gershgorin ----
    #pragma unroll
    for (int nn = 0; nn < PER; nn++) {
        int i = tid + nn * NT;
        int col = i & 63, row = i >> 6;
        bool dirI = (inflow[i] == 1);
        if (col < 63) {
            bool dirE = (inflow[i + 1] == 1);
            S.cEd[i + 64] = (dirI || dirE) ? 0.0
                          : S.cEd[i + 64] * S.isd[i] * S.isd[i + 1];
        }
        if (row < 63) {
            bool dirS = (inflow[i + 64] == 1);
            S.cSd[i + 64] = (dirI || dirS) ? 0.0
                          : S.cSd[i + 64] * S.isd[i] * S.isd[i + 64];
        }
    }
    __syncthreads();
    double gmax = 1.0;
    #pragma unroll
    for (int nn = 0; nn < PER; nn++) {
        int i = tid + nn * NT;
        double srow = 1.0 - (S.cEd[i + 64] + S.cEd[i + 63]
                           + S.cSd[i + 64] + S.cSd[i]);
        gmax = fmax(gmax, srow);
    }
    const double lmax = bred_dmax(gmax, S.red, tid) * 1.0005;

    // Chebyshev constants -- WIDE interval [b/120, b], degree 10
    const float bF = (float)lmax;
    const float aF = bF * (1.0f / 120.0f);
    const float thetaF = 0.5f * (bF + aF);
    const float deltaF = 0.5f * (bF - aF);
    const float inv_th = 1.0f / thetaF;
    const float sigma1 = thetaF / deltaF;
    const float rho0C  = 1.0f / sigma1;
    const float two_sg = 2.0f * sigma1;
    const float two_id = 2.0f / deltaF;

    // ---- 5. packed band coefficients ----
    const int row0 = wrp * 4, col0 = ln * 2;
    int jbase[4];
    ull cA[4], cB[4], cSp[4], cN0p;   // cA=(cW,cE0) cB=(cE0,cE1) cSp=(cS0,cS1)
    #pragma unroll
    for (int rr = 0; rr < 4; rr++) {
        int j = (row0 + rr) * 64 + col0 + 64;
        jbase[rr] = j;
        float e0 = (float)S.cEd[j], e1 = (float)S.cEd[j + 1];
        float w0 = (float)S.cEd[j - 1];
        float s0 = (float)S.cSd[j], s1 = (float)S.cSd[j + 1];
        PACK2(cA[rr], w0, e0);
        PACK2(cB[rr], e0, e1);
        PACK2(cSp[rr], s0, s1);
    }
    {
        float n0 = (float)S.cSd[jbase[0] - 64], n1 = (float)S.cSd[jbase[0] - 63];
        PACK2(cN0p, n0, n1);
    }
    ull NEG1, INVTH;
    PACK2(NEG1, -1.f, -1.f);
    PACK2(INVTH, inv_th, inv_th);

    double sb = 0.0;
    #pragma unroll
    for (int rr = 0; rr < 4; rr++) {
        double v0 = S.Bt[jbase[rr] - 64], v1 = S.Bt[jbase[rr] - 63];
        sb += v0 * v0 + v1 * v1;
    }
    const double rzb = bred_d(sb, S.red, tid);
    const double rz_target = rzb * 1e-16;

    // packed SpMV: t2 = A~ v2 ; ghosts (8B) from buffer buf
    auto spmv2 = [&](const ull v2[4], ull t2[4], int buf) {
        ull gN = *(const ull*)&S.gBot[buf][wrp][col0];      // row row0-1 pair
        ull gS = *(const ull*)&S.gTop[buf][wrp + 2][col0];  // row row0+4 pair
        #pragma unroll
        for (int rr = 0; rr < 4; rr++) {
            float vl, vr;
            UNPACK2(vl, vr, v2[rr]);
            float vW = __shfl_up_sync(0xffffffffu, vr, 1);
            float vE = __shfl_down_sync(0xffffffffu, vl, 1);
            ull xA, xB;
            PACK2(xA, vW, vl);
            PACK2(xB, vr, vE);
            ull n2 = (rr == 0) ? gN : v2[rr - 1];
            ull s2 = (rr == 3) ? gS : v2[rr + 1];
            ull cn = (rr == 0) ? cN0p : cSp[rr - 1];
            ull t;
            FMA2(t, cA[rr], xA, v2[rr]);
            FMA2(t, cB[rr], xB, t);
            FMA2(t, cn, n2, t);
            FMA2(t, cSp[rr], s2, t);
            t2[rr] = t;
        }
    };
    auto stage2 = [&](const ull v2[4], int buf) {
        *(ull*)&S.gTop[buf][wrp + 1][col0] = v2[0];
        *(ull*)&S.gBot[buf][wrp + 1][col0] = v2[3];
    };

    // ---- 6. outer refinement passes ----
    for (int pass = 0; pass < 6; ++pass) {
        // fp64 residual (band mapping)
        double rdv[8];
        double rr64 = 0.0;
        #pragma unroll
        for (int rr = 0; rr < 4; rr++) {
            #pragma unroll
            for (int cc = 0; cc < 2; cc++) {
                int j = jbase[rr] + cc;
                double qd = S.Zs[j]
                          + S.cEd[j]      * S.Zs[j + 1]
                          + S.cEd[j - 1]  * S.Zs[j - 1]
                          + S.cSd[j]      * S.Zs[j + 64]
                          + S.cSd[j - 64] * S.Zs[j - 64];
                double rv = S.Bt[j - 64] - qd;
                rdv[rr*2+cc] = rv;
                rr64 += rv * rv;
            }
        }
        rr64 = bred_d(rr64, S.red, tid);
        if (!(rr64 > rz_target)) break;

        ull r2[4], p2[4], q2[4], dx2[4];
        #pragma unroll
        for (int rr = 0; rr < 4; rr++) {
            PACK2(r2[rr], (float)rdv[rr*2+0], (float)rdv[rr*2+1]);
            p2[rr] = 0ull; q2[rr] = 0ull; dx2[rr] = 0ull;
        }
        const float tolp = fmaxf((float)rz_target, (float)rr64 * 1e-11f);
        const int cap = (pass == 0) ? 120 : 60;
        float rho_old = 1.f, alpha_old = 1.f;
        float rrchk = (float)rr64;

        for (int it = 0; it < cap; ++it) {
            // --- z = P_D(A) r, w = A z (Chebyshev, dot-free, packed) ---
            ull d2[4], z2[4], rin2[4], w2[4];
            #pragma unroll
            for (int rr = 0; rr < 4; rr++) {
                MUL2(d2[rr], r2[rr], INVTH);
                z2[rr] = d2[rr];
                rin2[rr] = r2[rr];
                w2[rr] = 0ull;
            }
            stage2(d2, 0);
            __syncthreads();
            float rhoC = rho0C;
            int buf = 0;
            #pragma unroll 1
            for (int k = 1; k <= CHEB_D; k++) {
                ull t2[4];
                spmv2(d2, t2, buf);
                float rhoN = __fdividef(1.f, two_sg - rhoC);
                float c1 = rhoN * rhoC, c2 = two_id * rhoN;
                ull c1p, c2p;
                PACK2(c1p, c1, c1);
                PACK2(c2p, c2, c2);
                #pragma unroll
                for (int rr = 0; rr < 4; rr++) {
                    FMA2(rin2[rr], t2[rr], NEG1, rin2[rr]);   // rin -= t
                    ADD2(w2[rr], w2[rr], t2[rr]);             // wacc += t
                    ull tmp;
                    MUL2(tmp, rin2[rr], c2p);
                    FMA2(d2[rr], d2[rr], c1p, tmp);           // d = c1*d + c2*rin
                    ADD2(z2[rr], z2[rr], d2[rr]);             // z += d
                }
                rhoC = rhoN;
                buf ^= 1;
                stage2(d2, buf);
                __syncthreads();
            }
            {
                ull t2[4];
                spmv2(d2, t2, buf);
                #pragma unroll
                for (int rr = 0; rr < 4; rr++) ADD2(w2[rr], w2[rr], t2[rr]);
            }

            // --- fused dots: rho=(r,z), mu=(z,w), rr=(r,r), packed partials ---
            ull apr = 0ull, apm = 0ull, aprr = 0ull;
            #pragma unroll
            for (int rr = 0; rr < 4; rr++) {
                FMA2(apr,  r2[rr], z2[rr], apr);
                FMA2(apm,  z2[rr], w2[rr], apm);
                FMA2(aprr, r2[rr], r2[rr], aprr);
            }
            float prL, prH, pmL, pmH, prrL, prrH;
            UNPACK2(prL, prH, apr);
            UNPACK2(pmL, pmH, apm);
            UNPACK2(prrL, prrH, aprr);
            float3 ds = bred3f(prL + prH, pmL + pmH, prrL + prrH, S.red4, tid);
            float rho = ds.x, mu = ds.y, rrf = ds.z;

            if (!(rrf > tolp)) break;
            if ((it & 15) == 15) {
                if (rrf > 0.9f * rrchk) break;
                rrchk = rrf;
            }
            if (!(rho > 0.f) || !(mu > 0.f)) break;

            float beta  = (it == 0) ? 0.f : __fdividef(rho, rho_old);
            float denom = mu - beta * __fdividef(rho, alpha_old);
            if (!(denom > 0.f)) break;
            float alpha = __fdividef(rho, denom);
            rho_old = rho; alpha_old = alpha;

            ull betap, alphap, nalphap;
            PACK2(betap, beta, beta);
            PACK2(alphap, alpha, alpha);
            PACK2(nalphap, -alpha, -alpha);
            #pragma unroll
            for (int rr = 0; rr < 4; rr++) {
                FMA2(p2[rr], p2[rr], betap, z2[rr]);      // p = z + beta p
                FMA2(q2[rr], q2[rr], betap, w2[rr]);      // q = w + beta q
                FMA2(dx2[rr], p2[rr], alphap, dx2[rr]);   // dx += alpha p
                FMA2(r2[rr], q2[rr], nalphap, r2[rr]);    // r -= alpha q
            }
            // next iter's stage(buf0) is WAR-safe: bred3f sync separates
        }

        __syncthreads();
        #pragma unroll
        for (int rr = 0; rr < 4; rr++) {
            float d0, d1;
            UNPACK2(d0, d1, dx2[rr]);
            S.Zs[jbase[rr] + 0] += (double)d0;
            S.Zs[jbase[rr] + 1] += (double)d1;
        }
        __syncthreads();
    }

    // ---- 7. outputs ----
    const double dtf = 3600.0;
    #pragma unroll
    for (int rr = 0; rr < 4; rr++) {
        #pragma unroll
        for (int cc = 0; cc < 2; cc++) {
            int i = jbase[rr] - 64 + cc;
            double x = S.Zs[i + 64] * S.isd[i];
            out[i] = (float)x;
            double P = (double)base[i] - x;
            const int* la = lan + 4 * i;
            double ssum = 0.0; int cnt = 0;
            #pragma unroll
            for (int k = 0; k < 4; k++) {
                int l = la[k];
                if (l >= 0) { ssum += (double)svel[l]; cnt++; }
            }
            double sliding = fabs(ssum / SEC_PER_A) / (double)(cnt > 0 ? cnt : 1);
            double nh = ((double)sheet[i] + dtf * sliding * HR_ / LR_)
                      / (1.0 + dtf * (sliding / LR_ + A_ * P * P * P));
            out[NN + i] = (float)nh;
        }
    }
}

extern "C" void kernel_launch(void* const* d_in, const int* in_sizes, int n_in,
                              void* d_out, int out_size)
{
    const float* base  = (const float*)d_in[0];
    const float* over  = (const float*)d_in[1];
    const float* melt  = (const float*)d_in[2];
    const float* sheet = (const float*)d_in[3];
    const float* pot   = (const float*)d_in[4];
    const float* svel  = (const float*)d_in[5];
    const float* llen  = (const float*)d_in[6];
    const int*   lan   = (const int*)d_in[9];
    const int*   infl  = (const int*)d_in[10];
    float* out = (float*)d_out;

    int smem = (int)sizeof(Smem);
    cudaFuncSetAttribute(sgd_kernel, cudaFuncAttributeMaxDynamicSharedMemorySize, smem);
    sgd_kernel<<<1, NT, smem>>>(base, over, melt, sheet, pot, svel, llen, lan, infl, out);
}